// round 13
// baseline (speedup 1.0000x reference)
#include <cuda_runtime.h>
#include <cuda_fp16.h>
#include <math.h>
#include <stdint.h>

#define D 128
#define NE 8192
#define NT 8192
#define EPSF 1e-8f

#define KT 128              // fp16 K
#define LDS_STRIDE 136      // padded smem row stride (elements)
#define BUF_BYTES (128 * LDS_STRIDE * 2)   // 34816 per fp16 buffer

// ---------------------------------------------------------------------------
// Device globals (no allocation allowed)
// ---------------------------------------------------------------------------
__device__ float g_h1[NE];
__device__ float g_h2[NT];
__device__ __align__(16) __half g_Ae[NE * KT];
__device__ __align__(16) __half g_At[NT * KT];
// C^T = (W@U_k)^T as fp16 hi/lo, layout [k][d]
__device__ __align__(16) __half g_CtrHi[D * D];
__device__ __align__(16) __half g_CtrLo[D * D];
// Q_hat as fp16 hi/lo, row-major (symmetric -> usable as col-major B)
__device__ __align__(16) __half g_QHi[D * D];
__device__ __align__(16) __half g_QLo[D * D];

// ---------------------------------------------------------------------------
__device__ __forceinline__ uint32_t smem_u32(const void* p) {
    uint32_t a;
    asm("{ .reg .u64 t; cvta.to.shared.u64 t, %1; cvt.u32.u64 %0, t; }"
        : "=r"(a) : "l"(p));
    return a;
}

__device__ __forceinline__ void cp_async16(uint32_t sdst, const void* gsrc) {
    asm volatile("cp.async.cg.shared.global [%0], [%1], 16;"
                 :: "r"(sdst), "l"(gsrc) : "memory");
}

#define CP_COMMIT() asm volatile("cp.async.commit_group;" ::: "memory")
#define CP_WAIT0()  asm volatile("cp.async.wait_group 0;" ::: "memory")

__device__ __forceinline__ void ldsm_x4(uint32_t (&r)[4], uint32_t addr) {
    asm volatile("ldmatrix.sync.aligned.m8n8.x4.shared.b16 {%0,%1,%2,%3}, [%4];"
                 : "=r"(r[0]), "=r"(r[1]), "=r"(r[2]), "=r"(r[3]) : "r"(addr));
}

__device__ __forceinline__ void mma16816(float (&d)[4], const uint32_t (&a)[4],
                                         uint32_t b0, uint32_t b1) {
    asm volatile(
        "mma.sync.aligned.m16n8k16.row.col.f32.f16.f16.f32 "
        "{%0,%1,%2,%3}, {%4,%5,%6,%7}, {%8,%9}, {%0,%1,%2,%3};"
        : "+f"(d[0]), "+f"(d[1]), "+f"(d[2]), "+f"(d[3])
        : "r"(a[0]), "r"(a[1]), "r"(a[2]), "r"(a[3]), "r"(b0), "r"(b1));
}

// ---------------------------------------------------------------------------
// build_C: C[d][k] = sum_i W[d][i]U[i][k]; emit Ctr (hi/lo, [k][d]) and
// Q_hat hi/lo (row-major copy). grid 128 (d), 128 threads (k).
// ---------------------------------------------------------------------------
__global__ __launch_bounds__(128)
void build_C_kernel(const float* __restrict__ W,
                    const float* __restrict__ U,
                    const float* __restrict__ Q) {
    __shared__ float Wrow[128];
    int d = blockIdx.x;
    int k = threadIdx.x;
    Wrow[k] = W[d * 128 + k];
    __syncthreads();

    float acc = 0.f;
#pragma unroll 16
    for (int i = 0; i < 128; i++)
        acc = fmaf(Wrow[i], U[i * 128 + k], acc);

    __half chi = __float2half_rn(acc);
    __half clo = __float2half_rn(acc - __half2float(chi));
    g_CtrHi[k * 128 + d] = chi;     // transposed store: [k][d]
    g_CtrLo[k * 128 + d] = clo;

    float q = Q[d * 128 + k];
    __half qhi = __float2half_rn(q);
    __half qlo = __float2half_rn(q - __half2float(qhi));
    g_QHi[d * 128 + k] = qhi;
    g_QLo[d * 128 + k] = qlo;
}

// ---------------------------------------------------------------------------
// project_tc: one CTA per 128 rows. grid (64, 2): y=0 enroll, y=1 test.
// 256 threads, 8 warps (2 m-groups x 4 n-groups, warp tile 64x32).
// ---------------------------------------------------------------------------
#define SM_VHI 0
#define SM_VLO (SM_VHI + BUF_BYTES)
#define SM_BHI (SM_VLO + BUF_BYTES)
#define SM_BLO (SM_BHI + BUF_BYTES)
#define SM_YHI (SM_BLO + BUF_BYTES)
#define SM_YLO (SM_YHI + BUF_BYTES)
#define SM_LAM (SM_YLO + BUF_BYTES)
#define SM_HSUM (SM_LAM + 512)
#define SM_RED (SM_HSUM + 512)
#define PROJ_SMEM (SM_RED + 512)

__global__ __launch_bounds__(256)
void project_tc(const float* __restrict__ Xe,
                const float* __restrict__ Xt,
                const float* __restrict__ miu,
                const float* __restrict__ lam) {
    extern __shared__ char sm[];
    uint32_t sb = smem_u32(sm);
    __half* vhi_s = (__half*)(sm + SM_VHI);
    __half* vlo_s = (__half*)(sm + SM_VLO);
    float* lam_s = (float*)(sm + SM_LAM);
    float* hsum = (float*)(sm + SM_HSUM);
    float* red = (float*)(sm + SM_RED);

    int tid = threadIdx.x;
    int lane = tid & 31, wid = tid >> 5;
    int which = blockIdx.y;
    int n0g = blockIdx.x * 128;
    const float* X = which ? Xt : Xe;

    // start Ctr loads (B operand of gemm1): 128 rows x 256 B = 2048 chunks
#pragma unroll
    for (int u = 0; u < 8; u++) {
        int c = u * 256 + tid;
        int row = c >> 4, cc = c & 15;
        cp_async16(sb + SM_BHI + (uint32_t)(row * LDS_STRIDE * 2 + cc * 16),
                   (const char*)g_CtrHi + row * 256 + cc * 16);
        cp_async16(sb + SM_BLO + (uint32_t)(row * LDS_STRIDE * 2 + cc * 16),
                   (const char*)g_CtrLo + row * 256 + cc * 16);
    }
    CP_COMMIT();

    if (tid < 128) { lam_s[tid] = lam[tid]; hsum[tid] = 0.f; }

    // ---- phase A: normalize, split v into hi/lo smem ----
    int t = tid & 127;
    int rg = tid >> 7;
    int w4 = (tid >> 5) & 3;
    float mu = miu[t];

#pragma unroll
    for (int ch = 0; ch < 4; ch++) {
        int rbase = rg * 64 + ch * 16;
        float xv[16];
#pragma unroll
        for (int i = 0; i < 16; i++)
            xv[i] = X[(size_t)(n0g + rbase + i) * D + t] - mu;
#pragma unroll
        for (int i = 0; i < 16; i++) {
            float s = xv[i] * xv[i];
#pragma unroll
            for (int o = 16; o > 0; o >>= 1)
                s += __shfl_xor_sync(0xffffffffu, s, o);
            if (lane == 0) red[rg * 64 + i * 4 + w4] = s;
        }
        __syncthreads();
#pragma unroll
        for (int i = 0; i < 16; i++) {
            int base = rg * 64 + i * 4;
            float tot = red[base] + red[base + 1] + red[base + 2] + red[base + 3];
            float vv = xv[i] / (sqrtf(tot) + EPSF);
            __half hi = __float2half_rn(vv);
            __half lo = __float2half_rn(vv - __half2float(hi));
            vhi_s[(rbase + i) * LDS_STRIDE + t] = hi;
            vlo_s[(rbase + i) * LDS_STRIDE + t] = lo;
        }
        __syncthreads();
    }

    CP_WAIT0();
    __syncthreads();

    int m0 = (wid >> 2) * 64;
    int n0 = (wid & 3) * 32;
    int rowA = lane & 15;
    int kselA = (lane >> 4) << 3;
    int nrow = ((lane >> 4) & 1) * 8 + (lane & 7);
    int kselB = ((lane >> 3) & 1) * 8;

    // ---- gemm1: Y = V * C, 3-term hi/lo ----
    float accY[4][4][4];
#pragma unroll
    for (int mi = 0; mi < 4; mi++)
#pragma unroll
        for (int nj = 0; nj < 4; nj++)
#pragma unroll
            for (int e = 0; e < 4; e++) accY[mi][nj][e] = 0.f;

#pragma unroll
    for (int term = 0; term < 3; term++) {
        uint32_t aB = sb + ((term == 2) ? SM_VLO : SM_VHI);
        uint32_t bB = sb + ((term == 1) ? SM_BLO : SM_BHI);
        uint32_t adA[4];
#pragma unroll
        for (int mi = 0; mi < 4; mi++)
            adA[mi] = aB + (uint32_t)((m0 + mi * 16 + rowA) * LDS_STRIDE + kselA) * 2u;
        uint32_t adB[2];
#pragma unroll
        for (int j = 0; j < 2; j++)
            adB[j] = bB + (uint32_t)((n0 + j * 16 + nrow) * LDS_STRIDE + kselB) * 2u;
#pragma unroll
        for (int k = 0; k < 8; k++) {
            uint32_t off = (uint32_t)k * 32u;
            uint32_t a[4][4];
#pragma unroll
            for (int mi = 0; mi < 4; mi++) ldsm_x4(a[mi], adA[mi] + off);
            uint32_t bfr[2][4];
#pragma unroll
            for (int j = 0; j < 2; j++) ldsm_x4(bfr[j], adB[j] + off);
#pragma unroll
            for (int mi = 0; mi < 4; mi++)
#pragma unroll
                for (int j = 0; j < 2; j++) {
                    mma16816(accY[mi][2 * j],     a[mi], bfr[j][0], bfr[j][1]);
                    mma16816(accY[mi][2 * j + 1], a[mi], bfr[j][2], bfr[j][3]);
                }
        }
    }
    __syncthreads();

    // start Q loads into B buffers
#pragma unroll
    for (int u = 0; u < 8; u++) {
        int c = u * 256 + tid;
        int row = c >> 4, cc = c & 15;
        cp_async16(sb + SM_BHI + (uint32_t)(row * LDS_STRIDE * 2 + cc * 16),
                   (const char*)g_QHi + row * 256 + cc * 16);
        cp_async16(sb + SM_BLO + (uint32_t)(row * LDS_STRIDE * 2 + cc * 16),
                   (const char*)g_QLo + row * 256 + cc * 16);
    }
    CP_COMMIT();

    // write Y (hi/lo) to smem and pack outputs to global
    __half* yhi_s = (__half*)(sm + SM_YHI);
    __half* ylo_s = (__half*)(sm + SM_YLO);
    __half* dst = which ? g_At : g_Ae;

#pragma unroll
    for (int mi = 0; mi < 4; mi++) {
        int r0 = m0 + mi * 16 + (lane >> 2);
        int r1 = r0 + 8;
#pragma unroll
        for (int nj = 0; nj < 4; nj++) {
            int c = n0 + nj * 8 + 2 * (lane & 3);
            float y00 = accY[mi][nj][0], y01 = accY[mi][nj][1];
            float y10 = accY[mi][nj][2], y11 = accY[mi][nj][3];

            __half h00 = __float2half_rn(y00), h01 = __float2half_rn(y01);
            __half h10 = __float2half_rn(y10), h11 = __float2half_rn(y11);
            *(__half2*)&yhi_s[r0 * LDS_STRIDE + c] = __halves2half2(h00, h01);
            *(__half2*)&yhi_s[r1 * LDS_STRIDE + c] = __halves2half2(h10, h11);
            *(__half2*)&ylo_s[r0 * LDS_STRIDE + c] =
                __halves2half2(__float2half_rn(y00 - __half2float(h00)),
                               __float2half_rn(y01 - __half2float(h01)));
            *(__half2*)&ylo_s[r1 * LDS_STRIDE + c] =
                __halves2half2(__float2half_rn(y10 - __half2float(h10)),
                               __float2half_rn(y11 - __half2float(h11)));

            float f0 = which ? 1.f : 2.f * lam_s[c];
            float f1 = which ? 1.f : 2.f * lam_s[c + 1];
            *(__half2*)&dst[(size_t)(n0g + r0) * KT + c] =
                __halves2half2(__float2half_rn(y00 * f0), __float2half_rn(y01 * f1));
            *(__half2*)&dst[(size_t)(n0g + r1) * KT + c] =
                __halves2half2(__float2half_rn(y10 * f0), __float2half_rn(y11 * f1));
        }
    }

    CP_WAIT0();
    __syncthreads();

    // ---- gemm2: Z = Y * Q, 3-term hi/lo ----
    float accZ[4][4][4];
#pragma unroll
    for (int mi = 0; mi < 4; mi++)
#pragma unroll
        for (int nj = 0; nj < 4; nj++)
#pragma unroll
            for (int e = 0; e < 4; e++) accZ[mi][nj][e] = 0.f;

#pragma unroll
    for (int term = 0; term < 3; term++) {
        uint32_t aB = sb + ((term == 2) ? SM_YLO : SM_YHI);
        uint32_t bB = sb + ((term == 1) ? SM_BLO : SM_BHI);
        uint32_t adA[4];
#pragma unroll
        for (int mi = 0; mi < 4; mi++)
            adA[mi] = aB + (uint32_t)((m0 + mi * 16 + rowA) * LDS_STRIDE + kselA) * 2u;
        uint32_t adB[2];
#pragma unroll
        for (int j = 0; j < 2; j++)
            adB[j] = bB + (uint32_t)((n0 + j * 16 + nrow) * LDS_STRIDE + kselB) * 2u;
#pragma unroll
        for (int k = 0; k < 8; k++) {
            uint32_t off = (uint32_t)k * 32u;
            uint32_t a[4][4];
#pragma unroll
            for (int mi = 0; mi < 4; mi++) ldsm_x4(a[mi], adA[mi] + off);
            uint32_t bfr[2][4];
#pragma unroll
            for (int j = 0; j < 2; j++) ldsm_x4(bfr[j], adB[j] + off);
#pragma unroll
            for (int mi = 0; mi < 4; mi++)
#pragma unroll
                for (int j = 0; j < 2; j++) {
                    mma16816(accZ[mi][2 * j],     a[mi], bfr[j][0], bfr[j][1]);
                    mma16816(accZ[mi][2 * j + 1], a[mi], bfr[j][2], bfr[j][3]);
                }
        }
    }

    // ---- h = sum_k Y[r][k] * Z[r][k] ----
#pragma unroll
    for (int mi = 0; mi < 4; mi++) {
        float p0 = 0.f, p1 = 0.f;
#pragma unroll
        for (int nj = 0; nj < 4; nj++) {
            p0 += accY[mi][nj][0] * accZ[mi][nj][0] +
                  accY[mi][nj][1] * accZ[mi][nj][1];
            p1 += accY[mi][nj][2] * accZ[mi][nj][2] +
                  accY[mi][nj][3] * accZ[mi][nj][3];
        }
        p0 += __shfl_xor_sync(0xffffffffu, p0, 1);
        p0 += __shfl_xor_sync(0xffffffffu, p0, 2);
        p1 += __shfl_xor_sync(0xffffffffu, p1, 1);
        p1 += __shfl_xor_sync(0xffffffffu, p1, 2);
        if ((lane & 3) == 0) {
            int r0 = m0 + mi * 16 + (lane >> 2);
            atomicAdd(&hsum[r0], p0);
            atomicAdd(&hsum[r0 + 8], p1);
        }
    }
    __syncthreads();

    if (tid < 128) {
        if (which == 0) g_h1[n0g + tid] = hsum[tid];
        else            g_h2[n0g + tid] = hsum[tid];
    }
}

// ---------------------------------------------------------------------------
// HMMA GEMM: 128(M) x 64(N) tile per CTA, 128 threads, 4 warps (2x2 of 64x32),
// 4 CTAs/SM. K=128 resident in smem.
// ---------------------------------------------------------------------------
#define GEMM_SMEM ((128 + 64) * LDS_STRIDE * 2)   // 52224

__global__ __launch_bounds__(128, 4)
void gemm_hmma(float* __restrict__ out) {
    extern __shared__ char sm[];
    uint32_t sA = smem_u32(sm);
    uint32_t sB = sA + 128 * LDS_STRIDE * 2;

    int tid = threadIdx.x;
    int lane = tid & 31, wid = tid >> 5;
    int bm0 = blockIdx.y * 128;
    int bn0 = blockIdx.x * 64;

    const char* gA = (const char*)(g_Ae + (size_t)bm0 * KT);
    const char* gB = (const char*)(g_At + (size_t)bn0 * KT);

    // A: 128 rows x 16 chunks = 2048; B: 64 rows x 16 chunks = 1024
#pragma unroll
    for (int u = 0; u < 24; u++) {
        int c = u * 128 + tid;           // 0..3071
        if (c < 2048) {
            int row = c >> 4, cc = c & 15;
            cp_async16(sA + (uint32_t)(row * LDS_STRIDE * 2 + cc * 16),
                       gA + row * (KT * 2) + cc * 16);
        } else {
            int c2 = c - 2048;
            int row = c2 >> 4, cc = c2 & 15;
            cp_async16(sB + (uint32_t)(row * LDS_STRIDE * 2 + cc * 16),
                       gB + row * (KT * 2) + cc * 16);
        }
    }
    CP_COMMIT();

    int m0 = (wid >> 1) * 64;      // 2 m-groups
    int n0 = (wid & 1) * 32;       // 2 n-groups
    int rowA = lane & 15;
    int kselA = (lane >> 4) << 3;
    uint32_t adA[4];
#pragma unroll
    for (int mi = 0; mi < 4; mi++)
        adA[mi] = sA + (uint32_t)((m0 + mi * 16 + rowA) * LDS_STRIDE + kselA) * 2u;
    int nrow = ((lane >> 4) & 1) * 8 + (lane & 7);
    int kselB = ((lane >> 3) & 1) * 8;
    uint32_t adB[2];
#pragma unroll
    for (int j = 0; j < 2; j++)
        adB[j] = sB + (uint32_t)((n0 + j * 16 + nrow) * LDS_STRIDE + kselB) * 2u;

    float acc[4][4][4];
#pragma unroll
    for (int mi = 0; mi < 4; mi++)
#pragma unroll
        for (int nj = 0; nj < 4; nj++)
#pragma unroll
            for (int e = 0; e < 4; e++) acc[mi][nj][e] = 0.f;

    CP_WAIT0();
    __syncthreads();

#pragma unroll
    for (int k = 0; k < 8; k++) {
        uint32_t off = (uint32_t)k * 32u;
        uint32_t a[4][4];
#pragma unroll
        for (int mi = 0; mi < 4; mi++) ldsm_x4(a[mi], adA[mi] + off);
        uint32_t bfr[2][4];
#pragma unroll
        for (int j = 0; j < 2; j++) ldsm_x4(bfr[j], adB[j] + off);
#pragma unroll
        for (int mi = 0; mi < 4; mi++)
#pragma unroll
            for (int j = 0; j < 2; j++) {
                mma16816(acc[mi][2 * j],     a[mi], bfr[j][0], bfr[j][1]);
                mma16816(acc[mi][2 * j + 1], a[mi], bfr[j][2], bfr[j][3]);
            }
    }

    int r0base = bm0 + m0 + (lane >> 2);
    int cbase = bn0 + n0 + 2 * (lane & 3);

    float h2v[4][2];
#pragma unroll
    for (int nj = 0; nj < 4; nj++) {
        h2v[nj][0] = g_h2[cbase + nj * 8];
        h2v[nj][1] = g_h2[cbase + nj * 8 + 1];
    }

#pragma unroll
    for (int mi = 0; mi < 4; mi++) {
        int gr0 = r0base + mi * 16;
        int gr1 = gr0 + 8;
        float h10 = g_h1[gr0];
        float h11 = g_h1[gr1];
#pragma unroll
        for (int nj = 0; nj < 4; nj++) {
            int gc = cbase + nj * 8;
            float2 v0 = make_float2(acc[mi][nj][0] + h10 + h2v[nj][0],
                                    acc[mi][nj][1] + h10 + h2v[nj][1]);
            float2 v1 = make_float2(acc[mi][nj][2] + h11 + h2v[nj][0],
                                    acc[mi][nj][3] + h11 + h2v[nj][1]);
            *(float2*)(out + (size_t)gr0 * NT + gc) = v0;
            *(float2*)(out + (size_t)gr1 * NT + gc) = v1;
        }
    }
}

// ---------------------------------------------------------------------------
extern "C" void kernel_launch(void* const* d_in, const int* in_sizes, int n_in,
                              void* d_out, int out_size) {
    const float* x_enroll = (const float*)d_in[0];
    const float* x_test   = (const float*)d_in[1];
    const float* W        = (const float*)d_in[2];
    const float* miu      = (const float*)d_in[3];
    const float* lam      = (const float*)d_in[4];
    const float* U_k      = (const float*)d_in[5];
    const float* Q_hat    = (const float*)d_in[6];
    float* out = (float*)d_out;

    build_C_kernel<<<128, 128>>>(W, U_k, Q_hat);

    cudaFuncSetAttribute(project_tc, cudaFuncAttributeMaxDynamicSharedMemorySize,
                         PROJ_SMEM);
    project_tc<<<dim3(64, 2), 256, PROJ_SMEM>>>(x_enroll, x_test, miu, lam);

    cudaFuncSetAttribute(gemm_hmma, cudaFuncAttributeMaxDynamicSharedMemorySize,
                         GEMM_SMEM);
    dim3 grid(NT / 64, NE / 128);
    gemm_hmma<<<grid, 128, GEMM_SMEM>>>(out);
}

// round 14
// speedup vs baseline: 1.0864x; 1.0864x over previous
#include <cuda_runtime.h>
#include <cuda_fp16.h>
#include <math.h>
#include <stdint.h>

#define D 128
#define NE 8192
#define NT 8192
#define EPSF 1e-8f

#define KT 128              // fp16 K
#define LDS_STRIDE 136      // padded smem row stride (elements)
#define BUF_BYTES (128 * LDS_STRIDE * 2)   // 34816 per fp16 buffer

// ---------------------------------------------------------------------------
// Device globals (no allocation allowed)
// ---------------------------------------------------------------------------
__device__ float g_h1[NE];
__device__ float g_h2[NT];
__device__ __align__(16) __half g_Ae[NE * KT];
__device__ __align__(16) __half g_At[NT * KT];
// C^T = (W@U_k)^T as fp16 hi/lo, layout [k][d]
__device__ __align__(16) __half g_CtrHi[D * D];
__device__ __align__(16) __half g_CtrLo[D * D];
// Q_hat as fp16 hi/lo, row-major (symmetric -> usable as col-major B)
__device__ __align__(16) __half g_QHi[D * D];
__device__ __align__(16) __half g_QLo[D * D];

// ---------------------------------------------------------------------------
__device__ __forceinline__ uint32_t smem_u32(const void* p) {
    uint32_t a;
    asm("{ .reg .u64 t; cvta.to.shared.u64 t, %1; cvt.u32.u64 %0, t; }"
        : "=r"(a) : "l"(p));
    return a;
}

__device__ __forceinline__ void cp_async16(uint32_t sdst, const void* gsrc) {
    asm volatile("cp.async.cg.shared.global [%0], [%1], 16;"
                 :: "r"(sdst), "l"(gsrc) : "memory");
}

#define CP_COMMIT() asm volatile("cp.async.commit_group;" ::: "memory")
#define CP_WAIT0()  asm volatile("cp.async.wait_group 0;" ::: "memory")
#define CP_WAIT1()  asm volatile("cp.async.wait_group 1;" ::: "memory")

__device__ __forceinline__ void ldsm_x4(uint32_t (&r)[4], uint32_t addr) {
    asm volatile("ldmatrix.sync.aligned.m8n8.x4.shared.b16 {%0,%1,%2,%3}, [%4];"
                 : "=r"(r[0]), "=r"(r[1]), "=r"(r[2]), "=r"(r[3]) : "r"(addr));
}

__device__ __forceinline__ void mma16816(float (&d)[4], const uint32_t (&a)[4],
                                         uint32_t b0, uint32_t b1) {
    asm volatile(
        "mma.sync.aligned.m16n8k16.row.col.f32.f16.f16.f32 "
        "{%0,%1,%2,%3}, {%4,%5,%6,%7}, {%8,%9}, {%0,%1,%2,%3};"
        : "+f"(d[0]), "+f"(d[1]), "+f"(d[2]), "+f"(d[3])
        : "r"(a[0]), "r"(a[1]), "r"(a[2]), "r"(a[3]), "r"(b0), "r"(b1));
}

// ---------------------------------------------------------------------------
// build_C: stage U (64KB) in smem via cp.async, then C[d][k] = sum_i W[d][i]U[i][k].
// grid 128 (d), 128 threads (k). Emits Ctr hi/lo ([k][d]) + Q hi/lo.
// ---------------------------------------------------------------------------
#define BC_SMEM (65536 + 512)

__global__ __launch_bounds__(128)
void build_C_kernel(const float* __restrict__ W,
                    const float* __restrict__ U,
                    const float* __restrict__ Q) {
    extern __shared__ char sm[];
    uint32_t sb = smem_u32(sm);
    float* Us = (float*)sm;                 // 64KB
    float* Wrow = (float*)(sm + 65536);     // 512B

    int d = blockIdx.x;
    int k = threadIdx.x;
    Wrow[k] = W[d * 128 + k];

    // stage U: 4096 16B chunks, 32 per thread
#pragma unroll
    for (int u = 0; u < 32; u++) {
        int c = u * 128 + k;
        cp_async16(sb + (uint32_t)c * 16u, (const char*)U + c * 16);
    }
    CP_COMMIT();
    CP_WAIT0();
    __syncthreads();

    float acc = 0.f;
#pragma unroll 16
    for (int i = 0; i < 128; i++)
        acc = fmaf(Wrow[i], Us[i * 128 + k], acc);

    __half chi = __float2half_rn(acc);
    __half clo = __float2half_rn(acc - __half2float(chi));
    g_CtrHi[k * 128 + d] = chi;     // transposed store: [k][d]
    g_CtrLo[k * 128 + d] = clo;

    float q = Q[d * 128 + k];
    __half qhi = __float2half_rn(q);
    __half qlo = __float2half_rn(q - __half2float(qhi));
    g_QHi[d * 128 + k] = qhi;
    g_QLo[d * 128 + k] = qlo;
}

// ---------------------------------------------------------------------------
// project_tc: one CTA per 128 rows. grid (64, 2): y=0 enroll, y=1 test.
// 256 threads, 8 warps. Q is prefetched at kernel start into YHI/YLO;
// after gemm1, Y overwrites BHI/BLO (Ctr dead), gemm2 uses swapped buffers.
// ---------------------------------------------------------------------------
#define SM_VHI 0
#define SM_VLO (SM_VHI + BUF_BYTES)
#define SM_BHI (SM_VLO + BUF_BYTES)
#define SM_BLO (SM_BHI + BUF_BYTES)
#define SM_YHI (SM_BLO + BUF_BYTES)
#define SM_YLO (SM_YHI + BUF_BYTES)
#define SM_LAM (SM_YLO + BUF_BYTES)
#define SM_HSUM (SM_LAM + 512)
#define SM_RED (SM_HSUM + 512)
#define PROJ_SMEM (SM_RED + 512)

__global__ __launch_bounds__(256)
void project_tc(const float* __restrict__ Xe,
                const float* __restrict__ Xt,
                const float* __restrict__ miu,
                const float* __restrict__ lam) {
    extern __shared__ char sm[];
    uint32_t sb = smem_u32(sm);
    __half* vhi_s = (__half*)(sm + SM_VHI);
    __half* vlo_s = (__half*)(sm + SM_VLO);
    float* lam_s = (float*)(sm + SM_LAM);
    float* hsum = (float*)(sm + SM_HSUM);
    float* red = (float*)(sm + SM_RED);

    int tid = threadIdx.x;
    int lane = tid & 31, wid = tid >> 5;
    int which = blockIdx.y;
    int n0g = blockIdx.x * 128;
    const float* X = which ? Xt : Xe;

    // group 1: Ctr -> BHI/BLO
#pragma unroll
    for (int u = 0; u < 8; u++) {
        int c = u * 256 + tid;
        int row = c >> 4, cc = c & 15;
        cp_async16(sb + SM_BHI + (uint32_t)(row * LDS_STRIDE * 2 + cc * 16),
                   (const char*)g_CtrHi + row * 256 + cc * 16);
        cp_async16(sb + SM_BLO + (uint32_t)(row * LDS_STRIDE * 2 + cc * 16),
                   (const char*)g_CtrLo + row * 256 + cc * 16);
    }
    CP_COMMIT();
    // group 2: Q -> YHI/YLO (used only by gemm2)
#pragma unroll
    for (int u = 0; u < 8; u++) {
        int c = u * 256 + tid;
        int row = c >> 4, cc = c & 15;
        cp_async16(sb + SM_YHI + (uint32_t)(row * LDS_STRIDE * 2 + cc * 16),
                   (const char*)g_QHi + row * 256 + cc * 16);
        cp_async16(sb + SM_YLO + (uint32_t)(row * LDS_STRIDE * 2 + cc * 16),
                   (const char*)g_QLo + row * 256 + cc * 16);
    }
    CP_COMMIT();

    if (tid < 128) { lam_s[tid] = lam[tid]; hsum[tid] = 0.f; }

    // ---- phase A: normalize, split v into hi/lo smem ----
    int t = tid & 127;
    int rg = tid >> 7;
    int w4 = (tid >> 5) & 3;
    float mu = miu[t];

#pragma unroll
    for (int ch = 0; ch < 4; ch++) {
        int rbase = rg * 64 + ch * 16;
        float xv[16];
#pragma unroll
        for (int i = 0; i < 16; i++)
            xv[i] = X[(size_t)(n0g + rbase + i) * D + t] - mu;
#pragma unroll
        for (int i = 0; i < 16; i++) {
            float s = xv[i] * xv[i];
#pragma unroll
            for (int o = 16; o > 0; o >>= 1)
                s += __shfl_xor_sync(0xffffffffu, s, o);
            if (lane == 0) red[rg * 64 + i * 4 + w4] = s;
        }
        __syncthreads();
#pragma unroll
        for (int i = 0; i < 16; i++) {
            int base = rg * 64 + i * 4;
            float tot = red[base] + red[base + 1] + red[base + 2] + red[base + 3];
            float vv = xv[i] / (sqrtf(tot) + EPSF);
            __half hi = __float2half_rn(vv);
            __half lo = __float2half_rn(vv - __half2float(hi));
            vhi_s[(rbase + i) * LDS_STRIDE + t] = hi;
            vlo_s[(rbase + i) * LDS_STRIDE + t] = lo;
        }
        __syncthreads();
    }

    CP_WAIT1();          // Ctr ready (Q may still be in flight)
    __syncthreads();

    int m0 = (wid >> 2) * 64;
    int n0 = (wid & 3) * 32;
    int rowA = lane & 15;
    int kselA = (lane >> 4) << 3;
    int nrow = ((lane >> 4) & 1) * 8 + (lane & 7);
    int kselB = ((lane >> 3) & 1) * 8;

    // ---- gemm1: Y = V * C, 3-term hi/lo (B from BHI/BLO) ----
    float accY[4][4][4];
#pragma unroll
    for (int mi = 0; mi < 4; mi++)
#pragma unroll
        for (int nj = 0; nj < 4; nj++)
#pragma unroll
            for (int e = 0; e < 4; e++) accY[mi][nj][e] = 0.f;

#pragma unroll
    for (int term = 0; term < 3; term++) {
        uint32_t aB = sb + ((term == 2) ? SM_VLO : SM_VHI);
        uint32_t bB = sb + ((term == 1) ? SM_BLO : SM_BHI);
        uint32_t adA[4];
#pragma unroll
        for (int mi = 0; mi < 4; mi++)
            adA[mi] = aB + (uint32_t)((m0 + mi * 16 + rowA) * LDS_STRIDE + kselA) * 2u;
        uint32_t adB[2];
#pragma unroll
        for (int j = 0; j < 2; j++)
            adB[j] = bB + (uint32_t)((n0 + j * 16 + nrow) * LDS_STRIDE + kselB) * 2u;
#pragma unroll
        for (int k = 0; k < 8; k++) {
            uint32_t off = (uint32_t)k * 32u;
            uint32_t a[4][4];
#pragma unroll
            for (int mi = 0; mi < 4; mi++) ldsm_x4(a[mi], adA[mi] + off);
            uint32_t bfr[2][4];
#pragma unroll
            for (int j = 0; j < 2; j++) ldsm_x4(bfr[j], adB[j] + off);
#pragma unroll
            for (int mi = 0; mi < 4; mi++)
#pragma unroll
                for (int j = 0; j < 2; j++) {
                    mma16816(accY[mi][2 * j],     a[mi], bfr[j][0], bfr[j][1]);
                    mma16816(accY[mi][2 * j + 1], a[mi], bfr[j][2], bfr[j][3]);
                }
        }
    }
    __syncthreads();   // done reading Ctr; BHI/BLO reusable for Y

    // write Y (hi/lo) into BHI/BLO and pack outputs to global
    __half* yhi_s = (__half*)(sm + SM_BHI);
    __half* ylo_s = (__half*)(sm + SM_BLO);
    __half* dst = which ? g_At : g_Ae;

#pragma unroll
    for (int mi = 0; mi < 4; mi++) {
        int r0 = m0 + mi * 16 + (lane >> 2);
        int r1 = r0 + 8;
#pragma unroll
        for (int nj = 0; nj < 4; nj++) {
            int c = n0 + nj * 8 + 2 * (lane & 3);
            float y00 = accY[mi][nj][0], y01 = accY[mi][nj][1];
            float y10 = accY[mi][nj][2], y11 = accY[mi][nj][3];

            __half h00 = __float2half_rn(y00), h01 = __float2half_rn(y01);
            __half h10 = __float2half_rn(y10), h11 = __float2half_rn(y11);
            *(__half2*)&yhi_s[r0 * LDS_STRIDE + c] = __halves2half2(h00, h01);
            *(__half2*)&yhi_s[r1 * LDS_STRIDE + c] = __halves2half2(h10, h11);
            *(__half2*)&ylo_s[r0 * LDS_STRIDE + c] =
                __halves2half2(__float2half_rn(y00 - __half2float(h00)),
                               __float2half_rn(y01 - __half2float(h01)));
            *(__half2*)&ylo_s[r1 * LDS_STRIDE + c] =
                __halves2half2(__float2half_rn(y10 - __half2float(h10)),
                               __float2half_rn(y11 - __half2float(h11)));

            float f0 = which ? 1.f : 2.f * lam_s[c];
            float f1 = which ? 1.f : 2.f * lam_s[c + 1];
            *(__half2*)&dst[(size_t)(n0g + r0) * KT + c] =
                __halves2half2(__float2half_rn(y00 * f0), __float2half_rn(y01 * f1));
            *(__half2*)&dst[(size_t)(n0g + r1) * KT + c] =
                __halves2half2(__float2half_rn(y10 * f0), __float2half_rn(y11 * f1));
        }
    }

    CP_WAIT0();
    __syncthreads();   // Y smem visible, Q (in YHI/YLO) ready

    // ---- gemm2: Z = Y * Q, 3-term hi/lo (A from BHI/BLO, B from YHI/YLO) ----
    float accZ[4][4][4];
#pragma unroll
    for (int mi = 0; mi < 4; mi++)
#pragma unroll
        for (int nj = 0; nj < 4; nj++)
#pragma unroll
            for (int e = 0; e < 4; e++) accZ[mi][nj][e] = 0.f;

#pragma unroll
    for (int term = 0; term < 3; term++) {
        uint32_t aB = sb + ((term == 2) ? SM_BLO : SM_BHI);
        uint32_t bB = sb + ((term == 1) ? SM_YLO : SM_YHI);
        uint32_t adA[4];
#pragma unroll
        for (int mi = 0; mi < 4; mi++)
            adA[mi] = aB + (uint32_t)((m0 + mi * 16 + rowA) * LDS_STRIDE + kselA) * 2u;
        uint32_t adB[2];
#pragma unroll
        for (int j = 0; j < 2; j++)
            adB[j] = bB + (uint32_t)((n0 + j * 16 + nrow) * LDS_STRIDE + kselB) * 2u;
#pragma unroll
        for (int k = 0; k < 8; k++) {
            uint32_t off = (uint32_t)k * 32u;
            uint32_t a[4][4];
#pragma unroll
            for (int mi = 0; mi < 4; mi++) ldsm_x4(a[mi], adA[mi] + off);
            uint32_t bfr[2][4];
#pragma unroll
            for (int j = 0; j < 2; j++) ldsm_x4(bfr[j], adB[j] + off);
#pragma unroll
            for (int mi = 0; mi < 4; mi++)
#pragma unroll
                for (int j = 0; j < 2; j++) {
                    mma16816(accZ[mi][2 * j],     a[mi], bfr[j][0], bfr[j][1]);
                    mma16816(accZ[mi][2 * j + 1], a[mi], bfr[j][2], bfr[j][3]);
                }
        }
    }

    // ---- h = sum_k Y[r][k] * Z[r][k] ----
#pragma unroll
    for (int mi = 0; mi < 4; mi++) {
        float p0 = 0.f, p1 = 0.f;
#pragma unroll
        for (int nj = 0; nj < 4; nj++) {
            p0 += accY[mi][nj][0] * accZ[mi][nj][0] +
                  accY[mi][nj][1] * accZ[mi][nj][1];
            p1 += accY[mi][nj][2] * accZ[mi][nj][2] +
                  accY[mi][nj][3] * accZ[mi][nj][3];
        }
        p0 += __shfl_xor_sync(0xffffffffu, p0, 1);
        p0 += __shfl_xor_sync(0xffffffffu, p0, 2);
        p1 += __shfl_xor_sync(0xffffffffu, p1, 1);
        p1 += __shfl_xor_sync(0xffffffffu, p1, 2);
        if ((lane & 3) == 0) {
            int r0 = m0 + mi * 16 + (lane >> 2);
            atomicAdd(&hsum[r0], p0);
            atomicAdd(&hsum[r0 + 8], p1);
        }
    }
    __syncthreads();

    if (tid < 128) {
        if (which == 0) g_h1[n0g + tid] = hsum[tid];
        else            g_h2[n0g + tid] = hsum[tid];
    }
}

// ---------------------------------------------------------------------------
// HMMA GEMM (round-12 proven): 128x128 tile, 256 threads, 2 CTAs/SM,
// register double-buffered fragments.
// ---------------------------------------------------------------------------
#define GEMM_SMEM (2 * 128 * LDS_STRIDE * 2)   // 69632

__global__ __launch_bounds__(256, 2)
void gemm_hmma(float* __restrict__ out) {
    extern __shared__ char sm[];
    uint32_t sA = smem_u32(sm);
    uint32_t sB = sA + 128 * LDS_STRIDE * 2;

    int tid = threadIdx.x;
    int lane = tid & 31, wid = tid >> 5;
    int bm0 = blockIdx.y * 128;
    int bn0 = blockIdx.x * 128;

    const char* gA = (const char*)(g_Ae + (size_t)bm0 * KT);
    const char* gB = (const char*)(g_At + (size_t)bn0 * KT);

#pragma unroll
    for (int u = 0; u < 16; u++) {
        int c = u * 256 + tid;           // 0..4095
        int tile = c >> 11;
        int row = (c >> 4) & 127;
        int cc = c & 15;
        const char* gsrc = (tile ? gB : gA) + row * (KT * 2) + cc * 16;
        uint32_t sdst = (tile ? sB : sA) +
                        (uint32_t)(row * LDS_STRIDE * 2 + cc * 16);
        cp_async16(sdst, gsrc);
    }
    CP_COMMIT();

    int m0 = (wid >> 2) * 64;
    int n0 = (wid & 3) * 32;
    int rowA = lane & 15;
    int kselA = (lane >> 4) << 3;
    uint32_t adA[4];
#pragma unroll
    for (int mi = 0; mi < 4; mi++)
        adA[mi] = sA + (uint32_t)((m0 + mi * 16 + rowA) * LDS_STRIDE + kselA) * 2u;
    int nrow = ((lane >> 4) & 1) * 8 + (lane & 7);
    int kselB = ((lane >> 3) & 1) * 8;
    uint32_t adB[2];
#pragma unroll
    for (int j = 0; j < 2; j++)
        adB[j] = sB + (uint32_t)((n0 + j * 16 + nrow) * LDS_STRIDE + kselB) * 2u;

    float acc[4][4][4];
#pragma unroll
    for (int mi = 0; mi < 4; mi++)
#pragma unroll
        for (int nj = 0; nj < 4; nj++)
#pragma unroll
            for (int e = 0; e < 4; e++) acc[mi][nj][e] = 0.f;

    CP_WAIT0();
    __syncthreads();

    uint32_t a[2][4][4];
    uint32_t bb[2][2][4];
#pragma unroll
    for (int mi = 0; mi < 4; mi++) ldsm_x4(a[0][mi], adA[mi]);
#pragma unroll
    for (int j = 0; j < 2; j++) ldsm_x4(bb[0][j], adB[j]);

#pragma unroll
    for (int k = 0; k < 8; k++) {
        int cur = k & 1, nxt = cur ^ 1;
        if (k < 7) {
            uint32_t off = (uint32_t)(k + 1) * 32u;
#pragma unroll
            for (int mi = 0; mi < 4; mi++) ldsm_x4(a[nxt][mi], adA[mi] + off);
#pragma unroll
            for (int j = 0; j < 2; j++) ldsm_x4(bb[nxt][j], adB[j] + off);
        }
#pragma unroll
        for (int mi = 0; mi < 4; mi++)
#pragma unroll
            for (int j = 0; j < 2; j++) {
                mma16816(acc[mi][2 * j],     a[cur][mi], bb[cur][j][0], bb[cur][j][1]);
                mma16816(acc[mi][2 * j + 1], a[cur][mi], bb[cur][j][2], bb[cur][j][3]);
            }
    }

    int r0base = bm0 + m0 + (lane >> 2);
    int cbase = bn0 + n0 + 2 * (lane & 3);

    float h2v[4][2];
#pragma unroll
    for (int nj = 0; nj < 4; nj++) {
        h2v[nj][0] = g_h2[cbase + nj * 8];
        h2v[nj][1] = g_h2[cbase + nj * 8 + 1];
    }

#pragma unroll
    for (int mi = 0; mi < 4; mi++) {
        int gr0 = r0base + mi * 16;
        int gr1 = gr0 + 8;
        float h10 = g_h1[gr0];
        float h11 = g_h1[gr1];
#pragma unroll
        for (int nj = 0; nj < 4; nj++) {
            int gc = cbase + nj * 8;
            float2 v0 = make_float2(acc[mi][nj][0] + h10 + h2v[nj][0],
                                    acc[mi][nj][1] + h10 + h2v[nj][1]);
            float2 v1 = make_float2(acc[mi][nj][2] + h11 + h2v[nj][0],
                                    acc[mi][nj][3] + h11 + h2v[nj][1]);
            *(float2*)(out + (size_t)gr0 * NT + gc) = v0;
            *(float2*)(out + (size_t)gr1 * NT + gc) = v1;
        }
    }
}

// ---------------------------------------------------------------------------
extern "C" void kernel_launch(void* const* d_in, const int* in_sizes, int n_in,
                              void* d_out, int out_size) {
    const float* x_enroll = (const float*)d_in[0];
    const float* x_test   = (const float*)d_in[1];
    const float* W        = (const float*)d_in[2];
    const float* miu      = (const float*)d_in[3];
    const float* lam      = (const float*)d_in[4];
    const float* U_k      = (const float*)d_in[5];
    const float* Q_hat    = (const float*)d_in[6];
    float* out = (float*)d_out;

    cudaFuncSetAttribute(build_C_kernel,
                         cudaFuncAttributeMaxDynamicSharedMemorySize, BC_SMEM);
    build_C_kernel<<<128, 128, BC_SMEM>>>(W, U_k, Q_hat);

    cudaFuncSetAttribute(project_tc, cudaFuncAttributeMaxDynamicSharedMemorySize,
                         PROJ_SMEM);
    project_tc<<<dim3(64, 2), 256, PROJ_SMEM>>>(x_enroll, x_test, miu, lam);

    cudaFuncSetAttribute(gemm_hmma, cudaFuncAttributeMaxDynamicSharedMemorySize,
                         GEMM_SMEM);
    dim3 grid(NT / 128, NE / 128);
    gemm_hmma<<<grid, 256, GEMM_SMEM>>>(out);
}